// round 15
// baseline (speedup 1.0000x reference)
#include <cuda_runtime.h>
#include <cuda_fp16.h>
#include <math.h>
#include <stdint.h>

// Problem dims (fixed)
#define BB 2
#define TT 2048
#define CC 1024
#define HH 16
#define HD 64
#define NROWS (BB*TT)          // 4096
#define FF (4*CC)              // 4096
#define QST 3072               // fused qkv row stride

// ---------------- scratch (__device__ globals; no allocs allowed) -----------
__device__ __half g_h   [NROWS*CC];    // LN1 out; later attn y; later LN2 out
__device__ __half g_qkv [NROWS*QST];   // fused qkv
__device__ float  g_x1  [NROWS*CC];    // x after attention residual (fp32)
__device__ __half g_m   [NROWS*FF];    // MLP hidden
__device__ __half g_wc  [QST*CC];      // fp16 [Wq;Wk;Wv]
__device__ __half g_wp  [CC*CC];       // fp16 Wp
__device__ __half g_w1  [FF*CC];       // fp16 W1
__device__ __half g_w2  [CC*FF];       // fp16 W2
__device__ float  g_bqkv[QST];         // bq|bk|bv fp32

// ---------------- setup: fp16 weight conversion (ILP-4) ---------------------
__global__ __launch_bounds__(256)
void wconv(const float4* __restrict__ src, __half2* __restrict__ dst, int n4)
{
    int i0 = blockIdx.x * 1024 + threadIdx.x;
    float4 v0, v1, v2, v3;
    const bool p0 = i0 < n4, p1 = i0 + 256 < n4, p2 = i0 + 512 < n4, p3 = i0 + 768 < n4;
    if (p0) v0 = src[i0];
    if (p1) v1 = src[i0 + 256];
    if (p2) v2 = src[i0 + 512];
    if (p3) v3 = src[i0 + 768];
    if (p0) { dst[2*i0]         = __floats2half2_rn(v0.x, v0.y);
              dst[2*i0+1]       = __floats2half2_rn(v0.z, v0.w); }
    if (p1) { dst[2*(i0+256)]   = __floats2half2_rn(v1.x, v1.y);
              dst[2*(i0+256)+1] = __floats2half2_rn(v1.z, v1.w); }
    if (p2) { dst[2*(i0+512)]   = __floats2half2_rn(v2.x, v2.y);
              dst[2*(i0+512)+1] = __floats2half2_rn(v2.z, v2.w); }
    if (p3) { dst[2*(i0+768)]   = __floats2half2_rn(v3.x, v3.y);
              dst[2*(i0+768)+1] = __floats2half2_rn(v3.z, v3.w); }
}
__global__ __launch_bounds__(1024)
void bias_concat(const float* __restrict__ bq, const float* __restrict__ bk,
                 const float* __restrict__ bv, float* __restrict__ dst)
{
    int i = threadIdx.x;
    dst[i]        = bq[i];
    dst[i + 1024] = bk[i];
    dst[i + 2048] = bv[i];
}

// ---------------- LayerNorm (fp32 in, fp16 out) ----------------
__global__ __launch_bounds__(256)
void ln_kernel(const float* __restrict__ x, const float* __restrict__ w,
               const float* __restrict__ b, __half* __restrict__ out)
{
    __shared__ float red[16];
    const int row = blockIdx.x;
    const int t = threadIdx.x;
    const float4* xr = (const float4*)(x + (size_t)row * CC);
    float4 v = xr[t];
    float s  = v.x + v.y + v.z + v.w;
    float ss = v.x*v.x + v.y*v.y + v.z*v.z + v.w*v.w;
    #pragma unroll
    for (int off = 16; off >= 1; off >>= 1) {
        s  += __shfl_xor_sync(0xffffffffu, s,  off);
        ss += __shfl_xor_sync(0xffffffffu, ss, off);
    }
    const int wid = t >> 5, lane = t & 31;
    if (lane == 0) { red[wid] = s; red[8 + wid] = ss; }
    __syncthreads();
    if (t == 0) {
        float S = 0.f, SS = 0.f;
        #pragma unroll
        for (int i = 0; i < 8; i++) { S += red[i]; SS += red[8 + i]; }
        red[0] = S; red[1] = SS;
    }
    __syncthreads();
    const float mu  = red[0] * (1.0f / CC);
    const float var = red[1] * (1.0f / CC) - mu * mu;
    const float rstd = rsqrtf(var + 1e-5f);
    const float4 wv = ((const float4*)w)[t];
    const float4 bv = ((const float4*)b)[t];
    __half2 h0 = __floats2half2_rn((v.x - mu) * rstd * wv.x + bv.x,
                                   (v.y - mu) * rstd * wv.y + bv.y);
    __half2 h1 = __floats2half2_rn((v.z - mu) * rstd * wv.z + bv.z,
                                   (v.w - mu) * rstd * wv.w + bv.w);
    __half2* orow = (__half2*)(out + (size_t)row * CC + 4 * t);
    orow[0] = h0; orow[1] = h1;
}

// ---------------- helpers ----------------
__device__ __forceinline__ float gelu_exact(float v) {
    return 0.5f * v * (1.0f + erff(v * 0.70710678118654752f));
}
__device__ __forceinline__ void mma_f16(float c[4], const uint32_t a[4],
                                        uint32_t b0, uint32_t b1) {
    asm volatile("mma.sync.aligned.m16n8k16.row.col.f32.f16.f16.f32 "
        "{%0,%1,%2,%3}, {%4,%5,%6,%7}, {%8,%9}, {%0,%1,%2,%3};\n"
        : "+f"(c[0]), "+f"(c[1]), "+f"(c[2]), "+f"(c[3])
        : "r"(a[0]), "r"(a[1]), "r"(a[2]), "r"(a[3]), "r"(b0), "r"(b1));
}
__device__ __forceinline__ void cp16(uint32_t s, const void* g) {
    asm volatile("cp.async.ca.shared.global [%0], [%1], 16;\n" :: "r"(s), "l"(g));
}
__device__ __forceinline__ void ldsm4(uint32_t r[4], uint32_t addr) {
    asm volatile("ldmatrix.sync.aligned.m8n8.x4.shared.b16 {%0,%1,%2,%3}, [%4];\n"
        : "=r"(r[0]), "=r"(r[1]), "=r"(r[2]), "=r"(r[3]) : "r"(addr));
}
__device__ __forceinline__ void ldsm2t(uint32_t& r0, uint32_t& r1, uint32_t addr) {
    asm volatile("ldmatrix.sync.aligned.m8n8.x2.trans.shared.b16 {%0,%1}, [%2];\n"
        : "=r"(r0), "=r"(r1) : "r"(addr));
}

// ---------------- fp16 tensor-core GEMM (unchanged from R14) ----------------
#define BM 128
#define BN 128
#define BK 32
#define LDSK 40                              // halfs; 80B row stride
#define STGB (BM * LDSK * 2)                 // 10240 B per operand-stage
#define GEMM_SMEM (2 * 2 * STGB)             // 40960 bytes

template<int ACT, bool RES, bool OUT16>
__device__ __forceinline__ void gemm_core(
    const __half* __restrict__ A, const __half* __restrict__ W,
    const float* __restrict__ bias, const float* __restrict__ res,
    void* __restrict__ outv, int K, int ldC,
    int m0, int n0w, int c0, char* gsm)
{
    const int t = threadIdx.x;
    const int wid  = t >> 5;
    const int lane = t & 31;
    const int g    = lane >> 2;
    const int tig  = lane & 3;
    const int wm = (wid & 1) * 64;
    const int wn = (wid >> 1) * 32;

    const uint32_t smA = (uint32_t)__cvta_generic_to_shared(gsm);
    const uint32_t smB = smA + 2 * STGB;

    const int lr = t >> 1;
    const int kh = (t & 1) * 16;
    const __half* ag = A + (size_t)(m0 + lr) * K + kh;
    const __half* bg = W + (size_t)(n0w + lr) * K + kh;
    const uint32_t as_s = smA + (lr * LDSK + kh) * 2;
    const uint32_t bs_s = smB + (lr * LDSK + kh) * 2;

    const uint32_t laneF = (uint32_t)(((lane & 15) * LDSK + (lane >> 4) * 8) * 2);
    const uint32_t aFragBase = smA + (uint32_t)(wm * LDSK * 2) + laneF;
    const uint32_t bFragBase = smB + (uint32_t)(wn * LDSK * 2) + laneF;

    float acc[4][4][4];
    #pragma unroll
    for (int mt = 0; mt < 4; mt++)
        #pragma unroll
        for (int nt = 0; nt < 4; nt++)
            #pragma unroll
            for (int r = 0; r < 4; r++) acc[mt][nt][r] = 0.f;

    const int KT = K / BK;
    cp16(as_s, ag);      cp16(as_s + 16, ag + 8);
    cp16(bs_s, bg);      cp16(bs_s + 16, bg + 8);
    asm volatile("cp.async.commit_group;\n");

    for (int kt = 0; kt < KT; ++kt) {
        asm volatile("cp.async.wait_group 0;\n");
        __syncthreads();

        if (kt + 1 < KT) {
            const __half* ag2 = ag + (size_t)(kt + 1) * BK;
            const __half* bg2 = bg + (size_t)(kt + 1) * BK;
            const uint32_t off = ((kt + 1) & 1) * STGB;
            cp16(as_s + off, ag2);  cp16(as_s + off + 16, ag2 + 8);
            cp16(bs_s + off, bg2);  cp16(bs_s + off + 16, bg2 + 8);
            asm volatile("cp.async.commit_group;\n");
        }

        const uint32_t abuf = aFragBase + (kt & 1) * STGB;
        const uint32_t bbuf = bFragBase + (kt & 1) * STGB;

        uint32_t af[2][4][4], bf[2][2][4];
        #pragma unroll
        for (int ks = 0; ks < 2; ++ks) {
            #pragma unroll
            for (int mt = 0; mt < 4; ++mt)
                ldsm4(af[ks][mt], abuf + (uint32_t)(mt * 16 * LDSK * 2) + ks * 32);
            #pragma unroll
            for (int np = 0; np < 2; ++np)
                ldsm4(bf[ks][np], bbuf + (uint32_t)(np * 16 * LDSK * 2) + ks * 32);
        }
        #pragma unroll
        for (int ks = 0; ks < 2; ++ks)
            #pragma unroll
            for (int mt = 0; mt < 4; ++mt)
                #pragma unroll
                for (int np = 0; np < 2; ++np) {
                    mma_f16(acc[mt][2*np],   af[ks][mt], bf[ks][np][0], bf[ks][np][2]);
                    mma_f16(acc[mt][2*np+1], af[ks][mt], bf[ks][np][1], bf[ks][np][3]);
                }
    }

    float* outF = (float*)outv;
    __half* outH = (__half*)outv;
    #pragma unroll
    for (int nt = 0; nt < 4; ++nt) {
        const int nloc = wn + nt * 8 + 2 * tig;
        const int col  = c0 + nloc;
        const float2 bc = *(const float2*)(bias + n0w + nloc);
        #pragma unroll
        for (int mt = 0; mt < 4; ++mt) {
            const int row = m0 + wm + mt * 16 + g;
            float v0 = acc[mt][nt][0] + bc.x;
            float v1 = acc[mt][nt][1] + bc.y;
            float v2 = acc[mt][nt][2] + bc.x;
            float v3 = acc[mt][nt][3] + bc.y;
            if (ACT == 1) {
                v0 = gelu_exact(v0); v1 = gelu_exact(v1);
                v2 = gelu_exact(v2); v3 = gelu_exact(v3);
            }
            if (RES) {
                const float2 r0 = *(const float2*)(res + (size_t)row * ldC + col);
                const float2 r1 = *(const float2*)(res + (size_t)(row + 8) * ldC + col);
                v0 += r0.x; v1 += r0.y; v2 += r1.x; v3 += r1.y;
            }
            if (OUT16) {
                *(__half2*)(outH + (size_t)row * ldC + col)       = __floats2half2_rn(v0, v1);
                *(__half2*)(outH + (size_t)(row + 8) * ldC + col) = __floats2half2_rn(v2, v3);
            } else {
                *(float2*)(outF + (size_t)row * ldC + col)       = make_float2(v0, v1);
                *(float2*)(outF + (size_t)(row + 8) * ldC + col) = make_float2(v2, v3);
            }
        }
    }
}

template<int ACT, bool RES, bool OUT16>
__global__ __launch_bounds__(256, 2)
void gemm3(const __half* __restrict__ A, const __half* __restrict__ W,
           const float* __restrict__ bias, const float* __restrict__ res,
           void* __restrict__ out, int K, int ldC)
{
    extern __shared__ char gsm[];
    gemm_core<ACT, RES, OUT16>(A, W, bias, res, out, K, ldC,
                               blockIdx.y * BM, blockIdx.x * BN, blockIdx.x * BN, gsm);
}

// ---------------- Flash attention, fp16, double-buffered cp.async KV --------
// BQ=128 (8 warps x m16), BKV=64, HD=64; 1 barrier per kv-tile.
#define ATS 72   // halfs; 144B row stride
// Q[128] + K0/K1/V0/V1 [64 each] + P[128] = 512 rows
#define ATTN_SMEM (512 * ATS * 2)   // 73728 bytes

__global__ __launch_bounds__(256, 2)
void attn_mma(const __half* __restrict__ qkv, __half* __restrict__ y)
{
    extern __shared__ __half sma[];
    __half* Qs = sma;                        // [128][ATS]
    __half* Ks = sma + 128 * ATS;            // [2][64][ATS]
    __half* Vs = sma + 256 * ATS;            // [2][64][ATS]
    __half* Ps = sma + 384 * ATS;            // [128][ATS]

    const int bh = blockIdx.x;
    const int b  = bh >> 4;
    const int h  = bh & 15;
    const int it = (int)gridDim.y - 1 - blockIdx.y;  // heavy tiles first
    const int t  = threadIdx.x;
    const int wid  = t >> 5;
    const int lane = t & 31;
    const int g    = lane >> 2;
    const int tig  = lane & 3;
    const int wm = wid * 16;
    const uint32_t ksb = (uint32_t)__cvta_generic_to_shared(Ks);
    const uint32_t vsb = (uint32_t)__cvta_generic_to_shared(Vs);

    // loader geometry for one 64x64 tile: fid covers 512 16B-chunks
    const int l_row0 = t >> 3;               // rows 0..31  (j=0)
    const int l_row1 = (t + 256) >> 3;       // rows 32..63 (j=1)
    const int l_d8   = (t & 7) * 8;

    // Q tile [128][64]: 4 uint4 per thread (plain loads)
    #pragma unroll
    for (int j = 0; j < 4; ++j) {
        const int fid = t + j * 256;
        const int row = fid >> 3;
        const int d8  = (fid & 7) * 8;
        *(uint4*)&Qs[row * ATS + d8] =
            *(const uint4*)(qkv + (size_t)(b * TT + it * 128 + row) * QST + h * HD + d8);
    }

    // prologue: prefetch KV[0] into buffer 0
    {
        const size_t r0 = (size_t)(b * TT + l_row0) * QST + h * HD + l_d8;
        const size_t r1 = (size_t)(b * TT + l_row1) * QST + h * HD + l_d8;
        cp16(ksb + (l_row0 * ATS + l_d8) * 2, qkv + r0 + CC);
        cp16(ksb + (l_row1 * ATS + l_d8) * 2, qkv + r1 + CC);
        cp16(vsb + (l_row0 * ATS + l_d8) * 2, qkv + r0 + 2 * CC);
        cp16(vsb + (l_row1 * ATS + l_d8) * 2, qkv + r1 + 2 * CC);
        asm volatile("cp.async.commit_group;\n");
    }

    float oc[8][4];
    #pragma unroll
    for (int nt = 0; nt < 8; ++nt)
        #pragma unroll
        for (int r = 0; r < 4; ++r) oc[nt][r] = 0.f;
    float m0 = -INFINITY, m1 = -INFINITY, l0 = 0.f, l1 = 0.f;

    const int JT = 2 * it + 2;
    for (int jt = 0; jt < JT; ++jt) {
        const int buf = jt & 1;
        asm volatile("cp.async.wait_group 0;\n");
        __syncthreads();   // KV[jt] visible; all warps done with KV[jt-1]

        if (jt + 1 < JT) { // prefetch KV[jt+1] into the other buffer
            const uint32_t ob = (uint32_t)((buf ^ 1) * 64 * ATS * 2);
            const size_t r0 = (size_t)(b * TT + (jt + 1) * 64 + l_row0) * QST + h * HD + l_d8;
            const size_t r1 = (size_t)(b * TT + (jt + 1) * 64 + l_row1) * QST + h * HD + l_d8;
            cp16(ksb + ob + (l_row0 * ATS + l_d8) * 2, qkv + r0 + CC);
            cp16(ksb + ob + (l_row1 * ATS + l_d8) * 2, qkv + r1 + CC);
            cp16(vsb + ob + (l_row0 * ATS + l_d8) * 2, qkv + r0 + 2 * CC);
            cp16(vsb + ob + (l_row1 * ATS + l_d8) * 2, qkv + r1 + 2 * CC);
            asm volatile("cp.async.commit_group;\n");
        }

        const __half* Kb = Ks + buf * 64 * ATS;
        const uint32_t vbB = vsb + (uint32_t)(buf * 64 * ATS * 2);

        // S = Q @ K^T
        float sc[8][4];
        #pragma unroll
        for (int nt = 0; nt < 8; ++nt)
            #pragma unroll
            for (int r = 0; r < 4; ++r) sc[nt][r] = 0.f;
        #pragma unroll
        for (int ks = 0; ks < 4; ++ks) {
            const int k0 = ks * 16;
            const int base = (wm + g) * ATS + k0 + 2 * tig;
            uint32_t a[4];
            a[0] = *(const uint32_t*)&Qs[base];
            a[1] = *(const uint32_t*)&Qs[base + 8 * ATS];
            a[2] = *(const uint32_t*)&Qs[base + 8];
            a[3] = *(const uint32_t*)&Qs[base + 8 * ATS + 8];
            #pragma unroll
            for (int nt = 0; nt < 8; ++nt) {
                const int nb = (nt * 8 + g) * ATS + k0 + 2 * tig;
                mma_f16(sc[nt], a, *(const uint32_t*)&Kb[nb],
                                   *(const uint32_t*)&Kb[nb + 8]);
            }
        }

        if (jt >= 2 * it) {
            const int r0 = it * 128 + wm + g;
            const int r1 = r0 + 8;
            const int cb = jt * 64 + 2 * tig;
            #pragma unroll
            for (int nt = 0; nt < 8; ++nt) {
                const int c0 = cb + nt * 8;
                if (c0     > r0) sc[nt][0] = -1e30f;
                if (c0 + 1 > r0) sc[nt][1] = -1e30f;
                if (c0     > r1) sc[nt][2] = -1e30f;
                if (c0 + 1 > r1) sc[nt][3] = -1e30f;
            }
        }

        float mx0 = -INFINITY, mx1 = -INFINITY;
        #pragma unroll
        for (int nt = 0; nt < 8; ++nt) {
            mx0 = fmaxf(mx0, fmaxf(sc[nt][0], sc[nt][1]));
            mx1 = fmaxf(mx1, fmaxf(sc[nt][2], sc[nt][3]));
        }
        mx0 = fmaxf(mx0, __shfl_xor_sync(0xffffffffu, mx0, 1));
        mx0 = fmaxf(mx0, __shfl_xor_sync(0xffffffffu, mx0, 2));
        mx1 = fmaxf(mx1, __shfl_xor_sync(0xffffffffu, mx1, 1));
        mx1 = fmaxf(mx1, __shfl_xor_sync(0xffffffffu, mx1, 2));
        const float mn0 = fmaxf(m0, mx0), mn1 = fmaxf(m1, mx1);
        const float cr0 = __expf((m0 - mn0) * 0.125f);
        const float cr1 = __expf((m1 - mn1) * 0.125f);
        m0 = mn0; m1 = mn1;
        float s0 = 0.f, s1 = 0.f;
        #pragma unroll
        for (int nt = 0; nt < 8; ++nt) {
            sc[nt][0] = __expf((sc[nt][0] - mn0) * 0.125f);
            sc[nt][1] = __expf((sc[nt][1] - mn0) * 0.125f);
            sc[nt][2] = __expf((sc[nt][2] - mn1) * 0.125f);
            sc[nt][3] = __expf((sc[nt][3] - mn1) * 0.125f);
            s0 += sc[nt][0] + sc[nt][1];
            s1 += sc[nt][2] + sc[nt][3];
            *(__half2*)&Ps[(wm + g) * ATS + nt * 8 + 2 * tig] =
                __floats2half2_rn(sc[nt][0], sc[nt][1]);
            *(__half2*)&Ps[(wm + g + 8) * ATS + nt * 8 + 2 * tig] =
                __floats2half2_rn(sc[nt][2], sc[nt][3]);
        }
        s0 += __shfl_xor_sync(0xffffffffu, s0, 1);
        s0 += __shfl_xor_sync(0xffffffffu, s0, 2);
        s1 += __shfl_xor_sync(0xffffffffu, s1, 1);
        s1 += __shfl_xor_sync(0xffffffffu, s1, 2);
        l0 = l0 * cr0 + s0;
        l1 = l1 * cr1 + s1;
        #pragma unroll
        for (int nt = 0; nt < 8; ++nt) {
            oc[nt][0] *= cr0; oc[nt][1] *= cr0;
            oc[nt][2] *= cr1; oc[nt][3] *= cr1;
        }

        // O += P @ V  (P: same-lane read-back; V resident since top-of-loop)
        #pragma unroll
        for (int ks = 0; ks < 4; ++ks) {
            const int k0 = ks * 16;
            const int base = (wm + g) * ATS + k0 + 2 * tig;
            uint32_t a[4];
            a[0] = *(const uint32_t*)&Ps[base];
            a[1] = *(const uint32_t*)&Ps[base + 8 * ATS];
            a[2] = *(const uint32_t*)&Ps[base + 8];
            a[3] = *(const uint32_t*)&Ps[base + 8 * ATS + 8];
            const uint32_t rowaddr = vbB + (uint32_t)(((k0 + (lane & 15)) * ATS) * 2);
            #pragma unroll
            for (int nt = 0; nt < 8; ++nt) {
                uint32_t b0, b1;
                ldsm2t(b0, b1, rowaddr + nt * 16);
                mma_f16(oc[nt], a, b0, b1);
            }
        }
    }

    // finalize + store y (fp16)
    const float inv0 = 1.0f / l0, inv1 = 1.0f / l1;
    const size_t r0 = (size_t)(b * TT + it * 128 + wm + g);
    #pragma unroll
    for (int nt = 0; nt < 8; ++nt) {
        const int col = h * HD + nt * 8 + 2 * tig;
        *(__half2*)(y + r0 * CC + col) =
            __floats2half2_rn(oc[nt][0] * inv0, oc[nt][1] * inv0);
        *(__half2*)(y + (r0 + 8) * CC + col) =
            __floats2half2_rn(oc[nt][2] * inv1, oc[nt][3] * inv1);
    }
}

// ---------------- launch ----------------
extern "C" void kernel_launch(void* const* d_in, const int* in_sizes, int n_in,
                              void* d_out, int out_size)
{
    (void)in_sizes; (void)n_in; (void)out_size;
    const float* x     = (const float*)d_in[0];
    const float* ln1_w = (const float*)d_in[1];
    const float* ln1_b = (const float*)d_in[2];
    const float* ln2_w = (const float*)d_in[3];
    const float* ln2_b = (const float*)d_in[4];
    const float* Wq    = (const float*)d_in[5];
    const float* bq    = (const float*)d_in[6];
    const float* Wk    = (const float*)d_in[7];
    const float* bk    = (const float*)d_in[8];
    const float* Wv    = (const float*)d_in[9];
    const float* bv    = (const float*)d_in[10];
    const float* Wp    = (const float*)d_in[11];
    const float* bp    = (const float*)d_in[12];
    const float* W1    = (const float*)d_in[13];
    const float* b1    = (const float*)d_in[14];
    const float* W2    = (const float*)d_in[15];
    const float* b2    = (const float*)d_in[16];
    float* out = (float*)d_out;

    __half *h, *qkv, *m, *wc, *wp, *w1, *w2;
    float *x1, *bqkv;
    cudaGetSymbolAddress((void**)&h,    g_h);
    cudaGetSymbolAddress((void**)&qkv,  g_qkv);
    cudaGetSymbolAddress((void**)&x1,   g_x1);
    cudaGetSymbolAddress((void**)&m,    g_m);
    cudaGetSymbolAddress((void**)&wc,   g_wc);
    cudaGetSymbolAddress((void**)&wp,   g_wp);
    cudaGetSymbolAddress((void**)&w1,   g_w1);
    cudaGetSymbolAddress((void**)&w2,   g_w2);
    cudaGetSymbolAddress((void**)&bqkv, g_bqkv);

    cudaFuncSetAttribute(gemm3<0,false,true >, cudaFuncAttributeMaxDynamicSharedMemorySize, GEMM_SMEM);
    cudaFuncSetAttribute(gemm3<0,true ,false>, cudaFuncAttributeMaxDynamicSharedMemorySize, GEMM_SMEM);
    cudaFuncSetAttribute(gemm3<1,false,true >, cudaFuncAttributeMaxDynamicSharedMemorySize, GEMM_SMEM);
    cudaFuncSetAttribute(attn_mma, cudaFuncAttributeMaxDynamicSharedMemorySize, ATTN_SMEM);

    // 0) setup: fp16 weights (ILP-4) + concat qkv bias
    const int N1 = CC*CC/4, N4 = FF*CC/4;
    wconv<<<N1/1024, 256>>>((const float4*)Wq, (__half2*)wc,             N1);
    wconv<<<N1/1024, 256>>>((const float4*)Wk, (__half2*)(wc + CC*CC),   N1);
    wconv<<<N1/1024, 256>>>((const float4*)Wv, (__half2*)(wc + 2*CC*CC), N1);
    wconv<<<N1/1024, 256>>>((const float4*)Wp, (__half2*)wp,             N1);
    wconv<<<N4/1024, 256>>>((const float4*)W1, (__half2*)w1,             N4);
    wconv<<<N4/1024, 256>>>((const float4*)W2, (__half2*)w2,             N4);
    bias_concat<<<1, 1024>>>(bq, bk, bv, bqkv);

    // 1) h = LN1(x)
    ln_kernel<<<NROWS, 256>>>(x, ln1_w, ln1_b, h);
    // 2) qkv = h @ Wcat^T + bcat  (fp16 out)
    gemm3<0,false,true><<<dim3(QST/BN, NROWS/BM), 256, GEMM_SMEM>>>(h, wc, bqkv, nullptr, qkv, CC, QST);
    // 3) y = causal-attention(qkv)  (into h, fp16)
    attn_mma<<<dim3(BB*HH, TT/128), 256, ATTN_SMEM>>>(qkv, h);
    // 4) x1 = x + y @ Wp^T + bp   (fp32 out)
    gemm3<0,true,false><<<dim3(CC/BN, NROWS/BM), 256, GEMM_SMEM>>>(h, wp, bp, x, x1, CC, CC);
    // 5) h2 = LN2(x1)  (into h, fp16)
    ln_kernel<<<NROWS, 256>>>(x1, ln2_w, ln2_b, h);
    // 6) m = gelu(h2 @ W1^T + b1)  (fp16 out)
    gemm3<1,false,true><<<dim3(FF/BN, NROWS/BM), 256, GEMM_SMEM>>>(h, w1, b1, nullptr, m, CC, FF);
    // 7) out = x1 + m @ W2^T + b2  (fp32 out)
    gemm3<0,true,false><<<dim3(CC/BN, NROWS/BM), 256, GEMM_SMEM>>>(m, w2, b2, x1, out, FF, CC);
}

// round 16
// speedup vs baseline: 1.5509x; 1.5509x over previous
#include <cuda_runtime.h>
#include <cuda_fp16.h>
#include <math.h>
#include <stdint.h>

// Problem dims (fixed)
#define BB 2
#define TT 2048
#define CC 1024
#define HH 16
#define HD 64
#define NROWS (BB*TT)          // 4096
#define FF (4*CC)              // 4096
#define QST 3072               // fused qkv row stride

// ---------------- scratch (__device__ globals; no allocs allowed) -----------
__device__ __half g_h   [NROWS*CC];    // LN1 out; later attn y; later LN2 out
__device__ __half g_qkv [NROWS*QST];   // fused qkv
__device__ float  g_x1  [NROWS*CC];    // x after attention residual (fp32)
__device__ __half g_m   [NROWS*FF];    // MLP hidden
__device__ __half g_wc  [QST*CC];      // fp16 [Wq;Wk;Wv]
__device__ __half g_wp  [CC*CC];       // fp16 Wp
__device__ __half g_w1  [FF*CC];       // fp16 W1
__device__ __half g_w2  [CC*FF];       // fp16 W2
__device__ float  g_bqkv[QST];         // bq|bk|bv fp32

// ---------------- setup: one fused fp16 weight-conversion launch ------------
// blocks 0-1023: Wq  | 1024-2047: Wk | 2048-3071: Wv | 3072-4095: Wp
// 4096-8191: W1 | 8192-12287: W2.  Each block converts 256 float4s.
__global__ __launch_bounds__(256)
void wconv6(const float4* __restrict__ q, const float4* __restrict__ k,
            const float4* __restrict__ v, const float4* __restrict__ p,
            const float4* __restrict__ w1s, const float4* __restrict__ w2s,
            __half2* __restrict__ wc, __half2* __restrict__ wp,
            __half2* __restrict__ w1d, __half2* __restrict__ w2d)
{
    const int bid = blockIdx.x;
    const float4* src; __half2* dst; int base;
    if (bid < 1024)      { src = q;   dst = wc;               base = bid; }
    else if (bid < 2048) { src = k;   dst = wc + CC*CC/2;     base = bid - 1024; }
    else if (bid < 3072) { src = v;   dst = wc + CC*CC;       base = bid - 2048; }
    else if (bid < 4096) { src = p;   dst = wp;               base = bid - 3072; }
    else if (bid < 8192) { src = w1s; dst = w1d;              base = bid - 4096; }
    else                 { src = w2s; dst = w2d;              base = bid - 8192; }
    const int i = base * 256 + threadIdx.x;
    const float4 vv = src[i];
    dst[2*i]   = __floats2half2_rn(vv.x, vv.y);
    dst[2*i+1] = __floats2half2_rn(vv.z, vv.w);
}
__global__ __launch_bounds__(1024)
void bias_concat(const float* __restrict__ bq, const float* __restrict__ bk,
                 const float* __restrict__ bv, float* __restrict__ dst)
{
    int i = threadIdx.x;
    dst[i]        = bq[i];
    dst[i + 1024] = bk[i];
    dst[i + 2048] = bv[i];
}

// ---------------- LayerNorm (fp32 in, fp16 out) ----------------
__global__ __launch_bounds__(256)
void ln_kernel(const float* __restrict__ x, const float* __restrict__ w,
               const float* __restrict__ b, __half* __restrict__ out)
{
    __shared__ float red[16];
    const int row = blockIdx.x;
    const int t = threadIdx.x;
    const float4* xr = (const float4*)(x + (size_t)row * CC);
    float4 v = xr[t];
    float s  = v.x + v.y + v.z + v.w;
    float ss = v.x*v.x + v.y*v.y + v.z*v.z + v.w*v.w;
    #pragma unroll
    for (int off = 16; off >= 1; off >>= 1) {
        s  += __shfl_xor_sync(0xffffffffu, s,  off);
        ss += __shfl_xor_sync(0xffffffffu, ss, off);
    }
    const int wid = t >> 5, lane = t & 31;
    if (lane == 0) { red[wid] = s; red[8 + wid] = ss; }
    __syncthreads();
    if (t == 0) {
        float S = 0.f, SS = 0.f;
        #pragma unroll
        for (int i = 0; i < 8; i++) { S += red[i]; SS += red[8 + i]; }
        red[0] = S; red[1] = SS;
    }
    __syncthreads();
    const float mu  = red[0] * (1.0f / CC);
    const float var = red[1] * (1.0f / CC) - mu * mu;
    const float rstd = rsqrtf(var + 1e-5f);
    const float4 wv = ((const float4*)w)[t];
    const float4 bv = ((const float4*)b)[t];
    __half2 h0 = __floats2half2_rn((v.x - mu) * rstd * wv.x + bv.x,
                                   (v.y - mu) * rstd * wv.y + bv.y);
    __half2 h1 = __floats2half2_rn((v.z - mu) * rstd * wv.z + bv.z,
                                   (v.w - mu) * rstd * wv.w + bv.w);
    __half2* orow = (__half2*)(out + (size_t)row * CC + 4 * t);
    orow[0] = h0; orow[1] = h1;
}

// ---------------- helpers ----------------
__device__ __forceinline__ float gelu_exact(float v) {
    return 0.5f * v * (1.0f + erff(v * 0.70710678118654752f));
}
__device__ __forceinline__ void mma_f16(float c[4], const uint32_t a[4],
                                        uint32_t b0, uint32_t b1) {
    asm volatile("mma.sync.aligned.m16n8k16.row.col.f32.f16.f16.f32 "
        "{%0,%1,%2,%3}, {%4,%5,%6,%7}, {%8,%9}, {%0,%1,%2,%3};\n"
        : "+f"(c[0]), "+f"(c[1]), "+f"(c[2]), "+f"(c[3])
        : "r"(a[0]), "r"(a[1]), "r"(a[2]), "r"(a[3]), "r"(b0), "r"(b1));
}
__device__ __forceinline__ void cp16(uint32_t s, const void* g) {
    asm volatile("cp.async.ca.shared.global [%0], [%1], 16;\n" :: "r"(s), "l"(g));
}
__device__ __forceinline__ void ldsm4(uint32_t r[4], uint32_t addr) {
    asm volatile("ldmatrix.sync.aligned.m8n8.x4.shared.b16 {%0,%1,%2,%3}, [%4];\n"
        : "=r"(r[0]), "=r"(r[1]), "=r"(r[2]), "=r"(r[3]) : "r"(addr));
}
__device__ __forceinline__ void ldsm2t(uint32_t& r0, uint32_t& r1, uint32_t addr) {
    asm volatile("ldmatrix.sync.aligned.m8n8.x2.trans.shared.b16 {%0,%1}, [%2];\n"
        : "=r"(r0), "=r"(r1) : "r"(addr));
}

// ---------------- fp16 tensor-core GEMM (R14 proven version) ----------------
#define BM 128
#define BN 128
#define BK 32
#define LDSK 40                              // halfs; 80B row stride
#define STGB (BM * LDSK * 2)                 // 10240 B per operand-stage
#define GEMM_SMEM (2 * 2 * STGB)             // 40960 bytes

template<int ACT, bool RES, bool OUT16>
__device__ __forceinline__ void gemm_core(
    const __half* __restrict__ A, const __half* __restrict__ W,
    const float* __restrict__ bias, const float* __restrict__ res,
    void* __restrict__ outv, int K, int ldC,
    int m0, int n0w, int c0, char* gsm)
{
    const int t = threadIdx.x;
    const int wid  = t >> 5;
    const int lane = t & 31;
    const int g    = lane >> 2;
    const int tig  = lane & 3;
    const int wm = (wid & 1) * 64;
    const int wn = (wid >> 1) * 32;

    const uint32_t smA = (uint32_t)__cvta_generic_to_shared(gsm);
    const uint32_t smB = smA + 2 * STGB;

    const int lr = t >> 1;
    const int kh = (t & 1) * 16;
    const __half* ag = A + (size_t)(m0 + lr) * K + kh;
    const __half* bg = W + (size_t)(n0w + lr) * K + kh;
    const uint32_t as_s = smA + (lr * LDSK + kh) * 2;
    const uint32_t bs_s = smB + (lr * LDSK + kh) * 2;

    const uint32_t laneF = (uint32_t)(((lane & 15) * LDSK + (lane >> 4) * 8) * 2);
    const uint32_t aFragBase = smA + (uint32_t)(wm * LDSK * 2) + laneF;
    const uint32_t bFragBase = smB + (uint32_t)(wn * LDSK * 2) + laneF;

    float acc[4][4][4];
    #pragma unroll
    for (int mt = 0; mt < 4; mt++)
        #pragma unroll
        for (int nt = 0; nt < 4; nt++)
            #pragma unroll
            for (int r = 0; r < 4; r++) acc[mt][nt][r] = 0.f;

    const int KT = K / BK;
    cp16(as_s, ag);      cp16(as_s + 16, ag + 8);
    cp16(bs_s, bg);      cp16(bs_s + 16, bg + 8);
    asm volatile("cp.async.commit_group;\n");

    for (int kt = 0; kt < KT; ++kt) {
        asm volatile("cp.async.wait_group 0;\n");
        __syncthreads();

        if (kt + 1 < KT) {
            const __half* ag2 = ag + (size_t)(kt + 1) * BK;
            const __half* bg2 = bg + (size_t)(kt + 1) * BK;
            const uint32_t off = ((kt + 1) & 1) * STGB;
            cp16(as_s + off, ag2);  cp16(as_s + off + 16, ag2 + 8);
            cp16(bs_s + off, bg2);  cp16(bs_s + off + 16, bg2 + 8);
            asm volatile("cp.async.commit_group;\n");
        }

        const uint32_t abuf = aFragBase + (kt & 1) * STGB;
        const uint32_t bbuf = bFragBase + (kt & 1) * STGB;

        uint32_t af[2][4][4], bf[2][2][4];
        #pragma unroll
        for (int ks = 0; ks < 2; ++ks) {
            #pragma unroll
            for (int mt = 0; mt < 4; ++mt)
                ldsm4(af[ks][mt], abuf + (uint32_t)(mt * 16 * LDSK * 2) + ks * 32);
            #pragma unroll
            for (int np = 0; np < 2; ++np)
                ldsm4(bf[ks][np], bbuf + (uint32_t)(np * 16 * LDSK * 2) + ks * 32);
        }
        #pragma unroll
        for (int ks = 0; ks < 2; ++ks)
            #pragma unroll
            for (int mt = 0; mt < 4; ++mt)
                #pragma unroll
                for (int np = 0; np < 2; ++np) {
                    mma_f16(acc[mt][2*np],   af[ks][mt], bf[ks][np][0], bf[ks][np][2]);
                    mma_f16(acc[mt][2*np+1], af[ks][mt], bf[ks][np][1], bf[ks][np][3]);
                }
    }

    float* outF = (float*)outv;
    __half* outH = (__half*)outv;
    #pragma unroll
    for (int nt = 0; nt < 4; ++nt) {
        const int nloc = wn + nt * 8 + 2 * tig;
        const int col  = c0 + nloc;
        const float2 bc = *(const float2*)(bias + n0w + nloc);
        #pragma unroll
        for (int mt = 0; mt < 4; ++mt) {
            const int row = m0 + wm + mt * 16 + g;
            float v0 = acc[mt][nt][0] + bc.x;
            float v1 = acc[mt][nt][1] + bc.y;
            float v2 = acc[mt][nt][2] + bc.x;
            float v3 = acc[mt][nt][3] + bc.y;
            if (ACT == 1) {
                v0 = gelu_exact(v0); v1 = gelu_exact(v1);
                v2 = gelu_exact(v2); v3 = gelu_exact(v3);
            }
            if (RES) {
                const float2 r0 = *(const float2*)(res + (size_t)row * ldC + col);
                const float2 r1 = *(const float2*)(res + (size_t)(row + 8) * ldC + col);
                v0 += r0.x; v1 += r0.y; v2 += r1.x; v3 += r1.y;
            }
            if (OUT16) {
                *(__half2*)(outH + (size_t)row * ldC + col)       = __floats2half2_rn(v0, v1);
                *(__half2*)(outH + (size_t)(row + 8) * ldC + col) = __floats2half2_rn(v2, v3);
            } else {
                *(float2*)(outF + (size_t)row * ldC + col)       = make_float2(v0, v1);
                *(float2*)(outF + (size_t)(row + 8) * ldC + col) = make_float2(v2, v3);
            }
        }
    }
}

template<int ACT, bool RES, bool OUT16>
__global__ __launch_bounds__(256, 2)
void gemm3(const __half* __restrict__ A, const __half* __restrict__ W,
           const float* __restrict__ bias, const float* __restrict__ res,
           void* __restrict__ out, int K, int ldC)
{
    extern __shared__ char gsm[];
    gemm_core<ACT, RES, OUT16>(A, W, bias, res, out, K, ldC,
                               blockIdx.y * BM, blockIdx.x * BN, blockIdx.x * BN, gsm);
}

// ---------------- Flash attention, fp16 (R14 structure + early V load) ------
#define ATS 72   // halfs; 144B row stride
#define ATTN_SMEM ((128*ATS + 64*ATS + 128*ATS) * 2)   // 46080 bytes

__global__ __launch_bounds__(256, 2)
void attn_mma(const __half* __restrict__ qkv, __half* __restrict__ y)
{
    extern __shared__ __half sma[];
    __half* Qs  = sma;                       // [128][ATS]
    __half* KVs = sma + 128 * ATS;           // [64][ATS]  (K then V, both [kv][d])
    __half* Ps  = sma + (128 + 64) * ATS;    // [128][ATS]

    const int bh = blockIdx.x;
    const int b  = bh >> 4;
    const int h  = bh & 15;
    const int it = (int)gridDim.y - 1 - blockIdx.y;  // heavy tiles first
    const int t  = threadIdx.x;
    const int wid  = t >> 5;
    const int lane = t & 31;
    const int g    = lane >> 2;
    const int tig  = lane & 3;
    const int wm = wid * 16;
    const uint32_t vbase = (uint32_t)__cvta_generic_to_shared(KVs);

    // loader geometry (two 16B chunks per thread per 64x64 tile)
    const int l_row0 = t >> 3;               // rows 0..31
    const int l_row1 = (t + 256) >> 3;       // rows 32..63
    const int l_d8   = (t & 7) * 8;

    // Q tile [128][64] halfs: 4 uint4 per thread
    #pragma unroll
    for (int j = 0; j < 4; ++j) {
        const int fid = t + j * 256;
        const int row = fid >> 3;
        const int d8  = (fid & 7) * 8;
        *(uint4*)&Qs[row * ATS + d8] =
            *(const uint4*)(qkv + (size_t)(b * TT + it * 128 + row) * QST + h * HD + d8);
    }

    float oc[8][4];
    #pragma unroll
    for (int nt = 0; nt < 8; ++nt)
        #pragma unroll
        for (int r = 0; r < 4; ++r) oc[nt][r] = 0.f;
    float m0 = -INFINITY, m1 = -INFINITY, l0 = 0.f, l1 = 0.f;

    const int JT = 2 * it + 2;
    for (int jt = 0; jt < JT; ++jt) {
        __syncthreads();
        // K tile [64][64]: 2 uint4 per thread
        {
            const size_t r0 = (size_t)(b * TT + jt * 64 + l_row0) * QST + CC + h * HD + l_d8;
            const size_t r1 = (size_t)(b * TT + jt * 64 + l_row1) * QST + CC + h * HD + l_d8;
            *(uint4*)&KVs[l_row0 * ATS + l_d8] = *(const uint4*)(qkv + r0);
            *(uint4*)&KVs[l_row1 * ATS + l_d8] = *(const uint4*)(qkv + r1);
        }
        __syncthreads();

        // stage V tile in registers NOW — latency hidden behind S + softmax
        uint4 vreg0, vreg1;
        {
            const size_t r0 = (size_t)(b * TT + jt * 64 + l_row0) * QST + 2 * CC + h * HD + l_d8;
            const size_t r1 = (size_t)(b * TT + jt * 64 + l_row1) * QST + 2 * CC + h * HD + l_d8;
            vreg0 = *(const uint4*)(qkv + r0);
            vreg1 = *(const uint4*)(qkv + r1);
        }

        // S = Q @ K^T
        float sc[8][4];
        #pragma unroll
        for (int nt = 0; nt < 8; ++nt)
            #pragma unroll
            for (int r = 0; r < 4; ++r) sc[nt][r] = 0.f;
        #pragma unroll
        for (int ks = 0; ks < 4; ++ks) {
            const int k0 = ks * 16;
            const int base = (wm + g) * ATS + k0 + 2 * tig;
            uint32_t a[4];
            a[0] = *(const uint32_t*)&Qs[base];
            a[1] = *(const uint32_t*)&Qs[base + 8 * ATS];
            a[2] = *(const uint32_t*)&Qs[base + 8];
            a[3] = *(const uint32_t*)&Qs[base + 8 * ATS + 8];
            #pragma unroll
            for (int nt = 0; nt < 8; ++nt) {
                const int nb = (nt * 8 + g) * ATS + k0 + 2 * tig;
                mma_f16(sc[nt], a, *(const uint32_t*)&KVs[nb],
                                   *(const uint32_t*)&KVs[nb + 8]);
            }
        }

        if (jt >= 2 * it) {
            const int r0 = it * 128 + wm + g;
            const int r1 = r0 + 8;
            const int cb = jt * 64 + 2 * tig;
            #pragma unroll
            for (int nt = 0; nt < 8; ++nt) {
                const int c0 = cb + nt * 8;
                if (c0     > r0) sc[nt][0] = -1e30f;
                if (c0 + 1 > r0) sc[nt][1] = -1e30f;
                if (c0     > r1) sc[nt][2] = -1e30f;
                if (c0 + 1 > r1) sc[nt][3] = -1e30f;
            }
        }

        float mx0 = -INFINITY, mx1 = -INFINITY;
        #pragma unroll
        for (int nt = 0; nt < 8; ++nt) {
            mx0 = fmaxf(mx0, fmaxf(sc[nt][0], sc[nt][1]));
            mx1 = fmaxf(mx1, fmaxf(sc[nt][2], sc[nt][3]));
        }
        mx0 = fmaxf(mx0, __shfl_xor_sync(0xffffffffu, mx0, 1));
        mx0 = fmaxf(mx0, __shfl_xor_sync(0xffffffffu, mx0, 2));
        mx1 = fmaxf(mx1, __shfl_xor_sync(0xffffffffu, mx1, 1));
        mx1 = fmaxf(mx1, __shfl_xor_sync(0xffffffffu, mx1, 2));
        const float mn0 = fmaxf(m0, mx0), mn1 = fmaxf(m1, mx1);
        const float cr0 = __expf((m0 - mn0) * 0.125f);
        const float cr1 = __expf((m1 - mn1) * 0.125f);
        m0 = mn0; m1 = mn1;
        float s0 = 0.f, s1 = 0.f;
        #pragma unroll
        for (int nt = 0; nt < 8; ++nt) {
            sc[nt][0] = __expf((sc[nt][0] - mn0) * 0.125f);
            sc[nt][1] = __expf((sc[nt][1] - mn0) * 0.125f);
            sc[nt][2] = __expf((sc[nt][2] - mn1) * 0.125f);
            sc[nt][3] = __expf((sc[nt][3] - mn1) * 0.125f);
            s0 += sc[nt][0] + sc[nt][1];
            s1 += sc[nt][2] + sc[nt][3];
            *(__half2*)&Ps[(wm + g) * ATS + nt * 8 + 2 * tig] =
                __floats2half2_rn(sc[nt][0], sc[nt][1]);
            *(__half2*)&Ps[(wm + g + 8) * ATS + nt * 8 + 2 * tig] =
                __floats2half2_rn(sc[nt][2], sc[nt][3]);
        }
        s0 += __shfl_xor_sync(0xffffffffu, s0, 1);
        s0 += __shfl_xor_sync(0xffffffffu, s0, 2);
        s1 += __shfl_xor_sync(0xffffffffu, s1, 1);
        s1 += __shfl_xor_sync(0xffffffffu, s1, 2);
        l0 = l0 * cr0 + s0;
        l1 = l1 * cr1 + s1;
        #pragma unroll
        for (int nt = 0; nt < 8; ++nt) {
            oc[nt][0] *= cr0; oc[nt][1] *= cr0;
            oc[nt][2] *= cr1; oc[nt][3] *= cr1;
        }
        __syncthreads();   // all warps done reading K

        // V tile store from registers (already loaded)
        *(uint4*)&KVs[l_row0 * ATS + l_d8] = vreg0;
        *(uint4*)&KVs[l_row1 * ATS + l_d8] = vreg1;
        __syncthreads();

        // O += P @ V  (V fragments via ldmatrix.x2.trans from [kv][d])
        #pragma unroll
        for (int ks = 0; ks < 4; ++ks) {
            const int k0 = ks * 16;
            const int base = (wm + g) * ATS + k0 + 2 * tig;
            uint32_t a[4];
            a[0] = *(const uint32_t*)&Ps[base];
            a[1] = *(const uint32_t*)&Ps[base + 8 * ATS];
            a[2] = *(const uint32_t*)&Ps[base + 8];
            a[3] = *(const uint32_t*)&Ps[base + 8 * ATS + 8];
            const uint32_t rowaddr = vbase + (uint32_t)(((k0 + (lane & 15)) * ATS) * 2);
            #pragma unroll
            for (int nt = 0; nt < 8; ++nt) {
                uint32_t b0, b1;
                ldsm2t(b0, b1, rowaddr + nt * 16);
                mma_f16(oc[nt], a, b0, b1);
            }
        }
    }

    // finalize + store y (fp16)
    const float inv0 = 1.0f / l0, inv1 = 1.0f / l1;
    const size_t r0 = (size_t)(b * TT + it * 128 + wm + g);
    #pragma unroll
    for (int nt = 0; nt < 8; ++nt) {
        const int col = h * HD + nt * 8 + 2 * tig;
        *(__half2*)(y + r0 * CC + col) =
            __floats2half2_rn(oc[nt][0] * inv0, oc[nt][1] * inv0);
        *(__half2*)(y + (r0 + 8) * CC + col) =
            __floats2half2_rn(oc[nt][2] * inv1, oc[nt][3] * inv1);
    }
}

// ---------------- launch ----------------
extern "C" void kernel_launch(void* const* d_in, const int* in_sizes, int n_in,
                              void* d_out, int out_size)
{
    (void)in_sizes; (void)n_in; (void)out_size;
    const float* x     = (const float*)d_in[0];
    const float* ln1_w = (const float*)d_in[1];
    const float* ln1_b = (const float*)d_in[2];
    const float* ln2_w = (const float*)d_in[3];
    const float* ln2_b = (const float*)d_in[4];
    const float* Wq    = (const float*)d_in[5];
    const float* bq    = (const float*)d_in[6];
    const float* Wk    = (const float*)d_in[7];
    const float* bk    = (const float*)d_in[8];
    const float* Wv    = (const float*)d_in[9];
    const float* bv    = (const float*)d_in[10];
    const float* Wp    = (const float*)d_in[11];
    const float* bp    = (const float*)d_in[12];
    const float* W1    = (const float*)d_in[13];
    const float* b1    = (const float*)d_in[14];
    const float* W2    = (const float*)d_in[15];
    const float* b2    = (const float*)d_in[16];
    float* out = (float*)d_out;

    __half *h, *qkv, *m, *wc, *wp, *w1, *w2;
    float *x1, *bqkv;
    cudaGetSymbolAddress((void**)&h,    g_h);
    cudaGetSymbolAddress((void**)&qkv,  g_qkv);
    cudaGetSymbolAddress((void**)&x1,   g_x1);
    cudaGetSymbolAddress((void**)&m,    g_m);
    cudaGetSymbolAddress((void**)&wc,   g_wc);
    cudaGetSymbolAddress((void**)&wp,   g_wp);
    cudaGetSymbolAddress((void**)&w1,   g_w1);
    cudaGetSymbolAddress((void**)&w2,   g_w2);
    cudaGetSymbolAddress((void**)&bqkv, g_bqkv);

    cudaFuncSetAttribute(gemm3<0,false,true >, cudaFuncAttributeMaxDynamicSharedMemorySize, GEMM_SMEM);
    cudaFuncSetAttribute(gemm3<0,true ,false>, cudaFuncAttributeMaxDynamicSharedMemorySize, GEMM_SMEM);
    cudaFuncSetAttribute(gemm3<1,false,true >, cudaFuncAttributeMaxDynamicSharedMemorySize, GEMM_SMEM);
    cudaFuncSetAttribute(attn_mma, cudaFuncAttributeMaxDynamicSharedMemorySize, ATTN_SMEM);

    // 0) setup: one fused fp16 weight conversion + concat qkv bias
    wconv6<<<12288, 256>>>((const float4*)Wq, (const float4*)Wk, (const float4*)Wv,
                           (const float4*)Wp, (const float4*)W1, (const float4*)W2,
                           (__half2*)wc, (__half2*)wp, (__half2*)w1, (__half2*)w2);
    bias_concat<<<1, 1024>>>(bq, bk, bv, bqkv);

    // 1) h = LN1(x)
    ln_kernel<<<NROWS, 256>>>(x, ln1_w, ln1_b, h);
    // 2) qkv = h @ Wcat^T + bcat  (fp16 out)
    gemm3<0,false,true><<<dim3(QST/BN, NROWS/BM), 256, GEMM_SMEM>>>(h, wc, bqkv, nullptr, qkv, CC, QST);
    // 3) y = causal-attention(qkv)  (into h, fp16)
    attn_mma<<<dim3(BB*HH, TT/128), 256, ATTN_SMEM>>>(qkv, h);
    // 4) x1 = x + y @ Wp^T + bp   (fp32 out)
    gemm3<0,true,false><<<dim3(CC/BN, NROWS/BM), 256, GEMM_SMEM>>>(h, wp, bp, x, x1, CC, CC);
    // 5) h2 = LN2(x1)  (into h, fp16)
    ln_kernel<<<NROWS, 256>>>(x1, ln2_w, ln2_b, h);
    // 6) m = gelu(h2 @ W1^T + b1)  (fp16 out)
    gemm3<1,false,true><<<dim3(FF/BN, NROWS/BM), 256, GEMM_SMEM>>>(h, w1, b1, nullptr, m, CC, FF);
    // 7) out = x1 + m @ W2^T + b2  (fp32 out)
    gemm3<0,true,false><<<dim3(CC/BN, NROWS/BM), 256, GEMM_SMEM>>>(m, w2, b2, x1, out, FF, CC);
}